// round 6
// baseline (speedup 1.0000x reference)
#include <cuda_runtime.h>
#include <cuda_bf16.h>
#include <cstdint>

#define NMAX 100000
#define EMAX 1600000
#define FDIM 128
#define GMAX 64
#define CLS  10
#define SCAN_B 1024

// ---- scratch (static device arrays; no cudaMalloc allowed) ----
__device__ float g_deg    [NMAX];
__device__ float g_dinv   [NMAX];
__device__ int   g_rcnt   [NMAX];
__device__ int   g_incl   [NMAX];
__device__ int   g_part   [256];
__device__ int   g_rowptr [NMAX + 1];
__device__ int   g_fill   [NMAX];
__device__ int   g_csrsrc [EMAX];
__device__ float g_csrw   [EMAX];
__device__ float g_T1  [NMAX * FDIM];
__device__ float g_T2  [NMAX * FDIM];
__device__ float g_H1  [NMAX * FDIM];
__device__ float g_H2  [NMAX * FDIM];
__device__ float g_sums[GMAX * FDIM];
__device__ float g_cnt [GMAX];
// pre-converted weights, k-interleaved layout, padded rows (136 bf16 per n-row):
// per layer: [src 0..2][ hi: 128*136 | lo: 128*136 ]  -> 34816 bf16 per src
__device__ __nv_bfloat16 g_Wc[3 * 3 * 34816];

// bf16-pair position of even k within a padded 136-elem row
__host__ __device__ __forceinline__ int kpos_even(int k) {
    int p = (k >> 1) & 7;
    return (k >> 4) * 16 + ((p & 3) << 2) + ((p >> 2) << 1);
}

// ================= norm prepass =================
__global__ void degcnt_kernel(const int* __restrict__ src, const int* __restrict__ dst, int E) {
    int e = blockIdx.x * blockDim.x + threadIdx.x;
    if (e < E) {
        atomicAdd(&g_deg[src[e]], 1.0f);
        atomicAdd(&g_rcnt[dst[e]], 1);
    }
}
__global__ void dinv_kernel(int n) {
    int i = blockIdx.x * blockDim.x + threadIdx.x;
    if (i < n) {
        float d = g_deg[i];
        g_dinv[i] = (d > 0.0f) ? rsqrtf(d) : 0.0f;
    }
}

// ================= CSR build (by dst) =================
__global__ void scan1_kernel(int n) {
    __shared__ int sm[SCAN_B];
    int i = blockIdx.x * SCAN_B + threadIdx.x;
    int v = (i < n) ? g_rcnt[i] : 0;
    sm[threadIdx.x] = v;
    __syncthreads();
    for (int off = 1; off < SCAN_B; off <<= 1) {
        int t = (threadIdx.x >= off) ? sm[threadIdx.x - off] : 0;
        __syncthreads();
        sm[threadIdx.x] += t;
        __syncthreads();
    }
    if (i < n) g_incl[i] = sm[threadIdx.x];
    if (threadIdx.x == SCAN_B - 1) g_part[blockIdx.x] = sm[threadIdx.x];
}
__global__ void scan2_kernel(int nb) {
    __shared__ int sm[256];
    int v = (threadIdx.x < nb) ? g_part[threadIdx.x] : 0;
    sm[threadIdx.x] = v;
    __syncthreads();
    for (int off = 1; off < 256; off <<= 1) {
        int t = (threadIdx.x >= off) ? sm[threadIdx.x - off] : 0;
        __syncthreads();
        sm[threadIdx.x] += t;
        __syncthreads();
    }
    if (threadIdx.x < nb) g_part[threadIdx.x] = sm[threadIdx.x] - v;
}
__global__ void scan3_kernel(int n) {
    int i = blockIdx.x * blockDim.x + threadIdx.x;
    if (i < n) g_rowptr[i + 1] = g_incl[i] + g_part[i / SCAN_B];
    if (i == 0) g_rowptr[0] = 0;
}
__global__ void fill_kernel(const int* __restrict__ src, const int* __restrict__ dst, int E) {
    int e = blockIdx.x * blockDim.x + threadIdx.x;
    if (e >= E) return;
    int d = dst[e], s = src[e];
    int p = g_rowptr[d] + atomicAdd(&g_fill[d], 1);
    g_csrsrc[p] = s;
    g_csrw[p]   = -g_dinv[s] * g_dinv[d];
}

// ================= CSR propagation: one warp per output row =================
// mode 0: OUT = Lhat*X ; mode 1: OUT = 2*(Lhat*X) - X0
template <int MODE>
__global__ void prop_csr_kernel(const float4* __restrict__ X, const float4* __restrict__ X0,
                                float4* __restrict__ OUT, int n) {
    int gw   = (blockIdx.x * blockDim.x + threadIdx.x) >> 5;
    if (gw >= n) return;
    int lane = threadIdx.x & 31;
    int p    = __ldg(&g_rowptr[gw]);
    int end  = __ldg(&g_rowptr[gw + 1]);
    float4 acc = make_float4(0.f, 0.f, 0.f, 0.f);
    for (; p + 3 < end; p += 4) {
        int   s0 = __ldg(&g_csrsrc[p]),   s1 = __ldg(&g_csrsrc[p+1]);
        int   s2 = __ldg(&g_csrsrc[p+2]), s3 = __ldg(&g_csrsrc[p+3]);
        float w0 = __ldg(&g_csrw[p]),     w1 = __ldg(&g_csrw[p+1]);
        float w2 = __ldg(&g_csrw[p+2]),   w3 = __ldg(&g_csrw[p+3]);
        float4 v0 = __ldg(&X[(long)s0 * 32 + lane]);
        float4 v1 = __ldg(&X[(long)s1 * 32 + lane]);
        float4 v2 = __ldg(&X[(long)s2 * 32 + lane]);
        float4 v3 = __ldg(&X[(long)s3 * 32 + lane]);
        acc.x += w0*v0.x + w1*v1.x + w2*v2.x + w3*v3.x;
        acc.y += w0*v0.y + w1*v1.y + w2*v2.y + w3*v3.y;
        acc.z += w0*v0.z + w1*v1.z + w2*v2.z + w3*v3.z;
        acc.w += w0*v0.w + w1*v1.w + w2*v2.w + w3*v3.w;
    }
    for (; p < end; ++p) {
        int   s = __ldg(&g_csrsrc[p]);
        float w = __ldg(&g_csrw[p]);
        float4 v = __ldg(&X[(long)s * 32 + lane]);
        acc.x += w*v.x; acc.y += w*v.y; acc.z += w*v.z; acc.w += w*v.w;
    }
    if (MODE == 1) {
        float4 u = __ldg(&X0[(long)gw * 32 + lane]);
        acc.x = 2.f * acc.x - u.x; acc.y = 2.f * acc.y - u.y;
        acc.z = 2.f * acc.z - u.z; acc.w = 2.f * acc.w - u.w;
    }
    OUT[(long)gw * 32 + lane] = acc;
}

// ================= weight pre-conversion =================
__global__ void wcvt_kernel(const float* __restrict__ W, __nv_bfloat16* __restrict__ out) {
    int e = blockIdx.x * blockDim.x + threadIdx.x;
    if (e >= 3 * 16384) return;
    int s   = e >> 14;
    int r   = e & 16383;
    int k   = r >> 7;
    int nn  = r & 127;
    float v = W[s * 16384 + (size_t)k * 128 + nn];
    __nv_bfloat16 h = __float2bfloat16(v);
    __nv_bfloat16 l = __float2bfloat16(v - __bfloat162float(h));
    int pos = kpos_even(k & ~1) + (k & 1);
    __nv_bfloat16* o = out + (size_t)s * 34816 + nn * 136 + pos;
    o[0]     = h;
    o[17408] = l;
}

// ================= bf16 mma.sync GEMM =================
// BM=64, BN=128, 8 warps (2M x 4N), warp tile 32x32. 2 CTAs/SM.
// MODE 0: OUT[row] = acc + bias (relu). MODE 2: red.global into g_sums[batch[row]].
#define APITCH 272
#define SMA_HI 0
#define SMA_LO (64 * APITCH)                // 17408
#define SMW_HI (2 * 64 * APITCH)            // 34816
#define SMW_LO (SMW_HI + 128 * APITCH)      // 69632
#define SM_GEMM (SMW_LO + 128 * APITCH)     // 104448

__device__ __forceinline__ void mma_bf16(float& d0, float& d1, float& d2, float& d3,
                                         uint32_t a0, uint32_t a1, uint32_t a2, uint32_t a3,
                                         uint32_t b0, uint32_t b1) {
    asm volatile("mma.sync.aligned.m16n8k16.row.col.f32.bf16.bf16.f32 "
                 "{%0,%1,%2,%3}, {%4,%5,%6,%7}, {%8,%9}, {%0,%1,%2,%3};"
                 : "+f"(d0), "+f"(d1), "+f"(d2), "+f"(d3)
                 : "r"(a0), "r"(a1), "r"(a2), "r"(a3), "r"(b0), "r"(b1));
}

template <int MODE>
__global__ void __launch_bounds__(256, 2) gemm_mma_kernel(
    const float* __restrict__ S0, const float* __restrict__ S1, const float* __restrict__ S2,
    const __nv_bfloat16* __restrict__ Wc, const float* __restrict__ bias,
    float* __restrict__ OUT, const int* __restrict__ batch, int n)
{
    extern __shared__ __align__(16) char smem[];
    const int tid  = threadIdx.x;
    const int wid  = tid >> 5;
    const int lane = tid & 31;
    const int wm   = wid & 1;          // rows wm*32
    const int wn   = wid >> 1;         // cols wn*32
    const int row0 = blockIdx.x * 64;

    float acc[2][4][4];
#pragma unroll
    for (int i = 0; i < 2; ++i)
#pragma unroll
        for (int j = 0; j < 4; ++j)
#pragma unroll
            for (int c = 0; c < 4; ++c) acc[i][j][c] = 0.0f;

    const int srow  = tid >> 2;           // staging row 0..63
    const int kbase = (tid & 3) * 32;     // staging k quarter

    for (int s = 0; s < 3; ++s) {
        const float* A = (s == 0) ? S0 : (s == 1) ? S1 : S2;
        __syncthreads();
        // ---- stage A (fp32 -> bf16 hi/lo, k-interleaved) ----
        {
            uint32_t* ah = (uint32_t*)(smem + SMA_HI + srow * APITCH);
            uint32_t* al = (uint32_t*)(smem + SMA_LO + srow * APITCH);
            const int rg = row0 + srow;
            const float4* arow = (const float4*)(A + (size_t)rg * FDIM + kbase);
#pragma unroll
            for (int j = 0; j < 8; ++j) {
                float4 v = (rg < n) ? __ldg(&arow[j]) : make_float4(0.f, 0.f, 0.f, 0.f);
                int k0 = kbase + 4 * j;
                __nv_bfloat16 h0 = __float2bfloat16(v.x), h1 = __float2bfloat16(v.y);
                __nv_bfloat16 h2 = __float2bfloat16(v.z), h3 = __float2bfloat16(v.w);
                __nv_bfloat16 l0 = __float2bfloat16(v.x - __bfloat162float(h0));
                __nv_bfloat16 l1 = __float2bfloat16(v.y - __bfloat162float(h1));
                __nv_bfloat16 l2 = __float2bfloat16(v.z - __bfloat162float(h2));
                __nv_bfloat16 l3 = __float2bfloat16(v.w - __bfloat162float(h3));
                int wA = kpos_even(k0) >> 1;
                int wB = kpos_even(k0 + 2) >> 1;
                union { __nv_bfloat162 b; uint32_t u; } t;
                t.b = __halves2bfloat162(h0, h1); ah[wA] = t.u;
                t.b = __halves2bfloat162(h2, h3); ah[wB] = t.u;
                t.b = __halves2bfloat162(l0, l1); al[wA] = t.u;
                t.b = __halves2bfloat162(l2, l3); al[wB] = t.u;
            }
        }
        // ---- stage W (already interleaved; straight copy) ----
        {
            const uint4* wsrc = (const uint4*)(Wc + (size_t)s * 34816);
            uint4* wdst = (uint4*)(smem + SMW_HI);
#pragma unroll
            for (int i = 0; i < 17; ++i)
                wdst[i * 256 + tid] = __ldg(&wsrc[i * 256 + tid]);
        }
        __syncthreads();

        // ---- 3 passes: (Ah,Wh), (Al,Wh), (Ah,Wl) ----
#pragma unroll
        for (int pass = 0; pass < 3; ++pass) {
            const char* abase = smem + ((pass == 1) ? SMA_LO : SMA_HI);
            const char* wbase = smem + ((pass == 2) ? SMW_LO : SMW_HI);
            const char* arow0 = abase + (wm * 32 + (lane >> 2)) * APITCH + (lane & 3) * 8;
            const char* brow0 = wbase + (wn * 32 + (lane >> 2)) * APITCH + (lane & 3) * 8;
#pragma unroll
            for (int g = 0; g < 8; ++g) {
                const int go = g * 32;
                uint2 a0 = *(const uint2*)(arow0 + go);
                uint2 a1 = *(const uint2*)(arow0 + 8 * APITCH + go);
                uint2 a2 = *(const uint2*)(arow0 + 16 * APITCH + go);
                uint2 a3 = *(const uint2*)(arow0 + 24 * APITCH + go);
                uint2 b[4];
#pragma unroll
                for (int j = 0; j < 4; ++j)
                    b[j] = *(const uint2*)(brow0 + j * 8 * APITCH + go);
#pragma unroll
                for (int j = 0; j < 4; ++j) {
                    mma_bf16(acc[0][j][0], acc[0][j][1], acc[0][j][2], acc[0][j][3],
                             a0.x, a1.x, a0.y, a1.y, b[j].x, b[j].y);
                    mma_bf16(acc[1][j][0], acc[1][j][1], acc[1][j][2], acc[1][j][3],
                             a2.x, a3.x, a2.y, a3.y, b[j].x, b[j].y);
                }
            }
        }
    }

    // ---- epilogue ----
#pragma unroll
    for (int i = 0; i < 2; ++i) {
        int r0 = row0 + wm * 32 + i * 16 + (lane >> 2);
        int r1 = r0 + 8;
        int g0 = 0, g1 = 0;
        if (MODE == 2) {
            if (r0 < n) g0 = __ldg(&batch[r0]);
            if (r1 < n) g1 = __ldg(&batch[r1]);
        }
#pragma unroll
        for (int j = 0; j < 4; ++j) {
            int col = wn * 32 + j * 8 + (lane & 3) * 2;
            float2 bv = __ldg((const float2*)&bias[col]);
            float2 o0 = make_float2(acc[i][j][0] + bv.x, acc[i][j][1] + bv.y);
            float2 o1 = make_float2(acc[i][j][2] + bv.x, acc[i][j][3] + bv.y);
            if (MODE == 0) {
                o0.x = fmaxf(o0.x, 0.f); o0.y = fmaxf(o0.y, 0.f);
                o1.x = fmaxf(o1.x, 0.f); o1.y = fmaxf(o1.y, 0.f);
                if (r0 < n) *(float2*)&OUT[(size_t)r0 * FDIM + col] = o0;
                if (r1 < n) *(float2*)&OUT[(size_t)r1 * FDIM + col] = o1;
            } else {
                if (r0 < n) {
                    float* p = &g_sums[g0 * FDIM + col];
                    asm volatile("red.global.add.v2.f32 [%0], {%1,%2};"
                                 :: "l"(p), "f"(o0.x), "f"(o0.y) : "memory");
                }
                if (r1 < n) {
                    float* p = &g_sums[g1 * FDIM + col];
                    asm volatile("red.global.add.v2.f32 [%0], {%1,%2};"
                                 :: "l"(p), "f"(o1.x), "f"(o1.y) : "memory");
                }
            }
        }
    }
}

// ================= pooling + classifier =================
__global__ void cnt_kernel(const int* __restrict__ batch, int n) {
    int i = blockIdx.x * blockDim.x + threadIdx.x;
    if (i < n) atomicAdd(&g_cnt[batch[i]], 1.0f);
}
__global__ void final_kernel(const float* __restrict__ Wl, const float* __restrict__ bl,
                             float* __restrict__ out, int ngraphs) {
    int tid = blockIdx.x * blockDim.x + threadIdx.x;
    if (tid >= ngraphs * CLS) return;
    int g = tid / CLS;
    int c = tid % CLS;
    float s = 0.0f;
    const float* sp = &g_sums[g * FDIM];
#pragma unroll 16
    for (int d = 0; d < FDIM; ++d) s = fmaf(sp[d], Wl[d * CLS + c], s);
    float cnt = fmaxf(g_cnt[g], 1.0f);
    out[g * CLS + c] = s / cnt + bl[c];
}

// ---------------------------------------------------------------
extern "C" void kernel_launch(void* const* d_in, const int* in_sizes, int n_in,
                              void* d_out, int out_size) {
    const float* x   = (const float*)d_in[0];
    const int*   ei  = (const int*)  d_in[1];
    const int*   bat = (const int*)  d_in[2];
    const float* W1  = (const float*)d_in[3];
    const float* b1  = (const float*)d_in[4];
    const float* W2  = (const float*)d_in[5];
    const float* b2  = (const float*)d_in[6];
    const float* W3  = (const float*)d_in[7];
    const float* b3  = (const float*)d_in[8];
    const float* Wl  = (const float*)d_in[9];
    const float* bl  = (const float*)d_in[10];
    float* out = (float*)d_out;

    const int n = in_sizes[0] / FDIM;          // 100000
    const int E = in_sizes[1] / 2;             // 1600000
    const int G = out_size / CLS;              // 64
    const int* src = ei;
    const int* dst = ei + E;
    const int ntiles = (n + 63) / 64;

    float *deg, *T1, *T2, *H1, *H2, *sums, *cnt;
    int *rcnt, *fill;
    __nv_bfloat16* Wc;
    cudaGetSymbolAddress((void**)&deg,  g_deg);
    cudaGetSymbolAddress((void**)&rcnt, g_rcnt);
    cudaGetSymbolAddress((void**)&fill, g_fill);
    cudaGetSymbolAddress((void**)&T1,   g_T1);
    cudaGetSymbolAddress((void**)&T2,   g_T2);
    cudaGetSymbolAddress((void**)&H1,   g_H1);
    cudaGetSymbolAddress((void**)&H2,   g_H2);
    cudaGetSymbolAddress((void**)&sums, g_sums);
    cudaGetSymbolAddress((void**)&cnt,  g_cnt);
    cudaGetSymbolAddress((void**)&Wc,   g_Wc);

    cudaFuncSetAttribute(gemm_mma_kernel<0>, cudaFuncAttributeMaxDynamicSharedMemorySize, SM_GEMM);
    cudaFuncSetAttribute(gemm_mma_kernel<2>, cudaFuncAttributeMaxDynamicSharedMemorySize, SM_GEMM);

    const int TB = 256;

    // degree / rcnt (one edge pass), normalization
    cudaMemsetAsync(deg,  0, (size_t)n * sizeof(float));
    cudaMemsetAsync(rcnt, 0, (size_t)n * sizeof(int));
    cudaMemsetAsync(fill, 0, (size_t)n * sizeof(int));
    cudaMemsetAsync(sums, 0, (size_t)G * FDIM * sizeof(float));
    cudaMemsetAsync(cnt,  0, (size_t)G * sizeof(float));
    degcnt_kernel<<<(E + TB - 1) / TB, TB>>>(src, dst, E);
    dinv_kernel<<<(n + TB - 1) / TB, TB>>>(n);

    // CSR build (by dst)
    const int nb = (n + SCAN_B - 1) / SCAN_B;
    scan1_kernel<<<nb, SCAN_B>>>(n);
    scan2_kernel<<<1, 256>>>(nb);
    scan3_kernel<<<(n + TB - 1) / TB, TB>>>(n);
    fill_kernel<<<(E + TB - 1) / TB, TB>>>(src, dst, E);

    // weight pre-conversion + graph counts
    const int wblk = (3 * 16384 + TB - 1) / TB;
    wcvt_kernel<<<wblk, TB>>>(W1, Wc);
    wcvt_kernel<<<wblk, TB>>>(W2, Wc + (size_t)3 * 34816);
    wcvt_kernel<<<wblk, TB>>>(W3, Wc + (size_t)6 * 34816);
    cnt_kernel<<<(n + TB - 1) / TB, TB>>>(bat, n);

    const int propBlocks = (n * 32 + TB - 1) / TB;

    // layer 1
    prop_csr_kernel<0><<<propBlocks, TB>>>((const float4*)x, nullptr, (float4*)T1, n);
    prop_csr_kernel<1><<<propBlocks, TB>>>((const float4*)T1, (const float4*)x, (float4*)T2, n);
    gemm_mma_kernel<0><<<ntiles, 256, SM_GEMM>>>(x, T1, T2, Wc, b1, H1, nullptr, n);
    // layer 2
    prop_csr_kernel<0><<<propBlocks, TB>>>((const float4*)H1, nullptr, (float4*)T1, n);
    prop_csr_kernel<1><<<propBlocks, TB>>>((const float4*)T1, (const float4*)H1, (float4*)T2, n);
    gemm_mma_kernel<0><<<ntiles, 256, SM_GEMM>>>(H1, T1, T2, Wc + (size_t)3 * 34816, b2, H2, nullptr, n);
    // layer 3 (pool fused into epilogue)
    prop_csr_kernel<0><<<propBlocks, TB>>>((const float4*)H2, nullptr, (float4*)T1, n);
    prop_csr_kernel<1><<<propBlocks, TB>>>((const float4*)T1, (const float4*)H2, (float4*)T2, n);
    gemm_mma_kernel<2><<<ntiles, 256, SM_GEMM>>>(H2, T1, T2, Wc + (size_t)6 * 34816, b3, nullptr, bat, n);

    // classifier
    final_kernel<<<(G * CLS + TB - 1) / TB, TB>>>(Wl, bl, out, G);
}

// round 7
// speedup vs baseline: 1.1209x; 1.1209x over previous
#include <cuda_runtime.h>
#include <cuda_bf16.h>
#include <cstdint>

#define NMAX 100000
#define EMAX 1600000
#define FDIM 128
#define GMAX 64
#define CLS  10
#define SCAN_B 1024

// ---- scratch (static device arrays; no cudaMalloc allowed) ----
__device__ float g_deg    [NMAX];
__device__ float g_dinv   [NMAX];
__device__ int   g_rcnt   [NMAX];
__device__ int   g_incl   [NMAX];
__device__ int   g_part   [256];
__device__ int   g_rowptr [NMAX + 1];
__device__ int   g_fill   [NMAX];
__device__ int   g_csrsrc [EMAX];
__device__ float g_csrw   [EMAX];
__device__ float g_T1  [NMAX * FDIM];
__device__ float g_T2  [NMAX * FDIM];
__device__ float g_H1  [NMAX * FDIM];
__device__ float g_H2  [NMAX * FDIM];
__device__ float g_sums[GMAX * FDIM];
__device__ float g_cnt [GMAX];
// pre-converted weights, k-interleaved layout, padded rows (136 bf16 per n-row):
// per layer: [src 0..2][ hi: 128*136 | lo: 128*136 ]  -> 34816 bf16 per src
__device__ __nv_bfloat16 g_Wc[3 * 3 * 34816];

// bf16-pair position of even k within a padded 136-elem row
__host__ __device__ __forceinline__ int kpos_even(int k) {
    int p = (k >> 1) & 7;
    return (k >> 4) * 16 + ((p & 3) << 2) + ((p >> 2) << 1);
}

// ================= norm prepass =================
__global__ void degcnt_kernel(const int* __restrict__ src, const int* __restrict__ dst, int E) {
    int e = blockIdx.x * blockDim.x + threadIdx.x;
    if (e < E) {
        atomicAdd(&g_deg[src[e]], 1.0f);
        atomicAdd(&g_rcnt[dst[e]], 1);
    }
}
__global__ void dinv_kernel(int n) {
    int i = blockIdx.x * blockDim.x + threadIdx.x;
    if (i < n) {
        float d = g_deg[i];
        g_dinv[i] = (d > 0.0f) ? rsqrtf(d) : 0.0f;
    }
}

// ================= CSR build (by dst) =================
__global__ void scan1_kernel(int n) {
    __shared__ int sm[SCAN_B];
    int i = blockIdx.x * SCAN_B + threadIdx.x;
    int v = (i < n) ? g_rcnt[i] : 0;
    sm[threadIdx.x] = v;
    __syncthreads();
    for (int off = 1; off < SCAN_B; off <<= 1) {
        int t = (threadIdx.x >= off) ? sm[threadIdx.x - off] : 0;
        __syncthreads();
        sm[threadIdx.x] += t;
        __syncthreads();
    }
    if (i < n) g_incl[i] = sm[threadIdx.x];
    if (threadIdx.x == SCAN_B - 1) g_part[blockIdx.x] = sm[threadIdx.x];
}
__global__ void scan2_kernel(int nb) {
    __shared__ int sm[256];
    int v = (threadIdx.x < nb) ? g_part[threadIdx.x] : 0;
    sm[threadIdx.x] = v;
    __syncthreads();
    for (int off = 1; off < 256; off <<= 1) {
        int t = (threadIdx.x >= off) ? sm[threadIdx.x - off] : 0;
        __syncthreads();
        sm[threadIdx.x] += t;
        __syncthreads();
    }
    if (threadIdx.x < nb) g_part[threadIdx.x] = sm[threadIdx.x] - v;
}
__global__ void scan3_kernel(int n) {
    int i = blockIdx.x * blockDim.x + threadIdx.x;
    if (i < n) g_rowptr[i + 1] = g_incl[i] + g_part[i / SCAN_B];
    if (i == 0) g_rowptr[0] = 0;
}
__global__ void fill_kernel(const int* __restrict__ src, const int* __restrict__ dst, int E) {
    int e = blockIdx.x * blockDim.x + threadIdx.x;
    if (e >= E) return;
    int d = dst[e], s = src[e];
    int p = g_rowptr[d] + atomicAdd(&g_fill[d], 1);
    g_csrsrc[p] = s;
    g_csrw[p]   = -g_dinv[s] * g_dinv[d];
}

// ================= CSR propagation: one warp per output row =================
// mode 0: OUT = Lhat*X ; mode 1: OUT = 2*(Lhat*X) - X0
template <int MODE>
__global__ void prop_csr_kernel(const float4* __restrict__ X, const float4* __restrict__ X0,
                                float4* __restrict__ OUT, int n) {
    int gw   = (blockIdx.x * blockDim.x + threadIdx.x) >> 5;
    if (gw >= n) return;
    int lane = threadIdx.x & 31;
    int p    = __ldg(&g_rowptr[gw]);
    int end  = __ldg(&g_rowptr[gw + 1]);
    float4 acc = make_float4(0.f, 0.f, 0.f, 0.f);
    for (; p + 3 < end; p += 4) {
        int   s0 = __ldg(&g_csrsrc[p]),   s1 = __ldg(&g_csrsrc[p+1]);
        int   s2 = __ldg(&g_csrsrc[p+2]), s3 = __ldg(&g_csrsrc[p+3]);
        float w0 = __ldg(&g_csrw[p]),     w1 = __ldg(&g_csrw[p+1]);
        float w2 = __ldg(&g_csrw[p+2]),   w3 = __ldg(&g_csrw[p+3]);
        float4 v0 = __ldg(&X[(long)s0 * 32 + lane]);
        float4 v1 = __ldg(&X[(long)s1 * 32 + lane]);
        float4 v2 = __ldg(&X[(long)s2 * 32 + lane]);
        float4 v3 = __ldg(&X[(long)s3 * 32 + lane]);
        acc.x += w0*v0.x + w1*v1.x + w2*v2.x + w3*v3.x;
        acc.y += w0*v0.y + w1*v1.y + w2*v2.y + w3*v3.y;
        acc.z += w0*v0.z + w1*v1.z + w2*v2.z + w3*v3.z;
        acc.w += w0*v0.w + w1*v1.w + w2*v2.w + w3*v3.w;
    }
    for (; p < end; ++p) {
        int   s = __ldg(&g_csrsrc[p]);
        float w = __ldg(&g_csrw[p]);
        float4 v = __ldg(&X[(long)s * 32 + lane]);
        acc.x += w*v.x; acc.y += w*v.y; acc.z += w*v.z; acc.w += w*v.w;
    }
    if (MODE == 1) {
        float4 u = __ldg(&X0[(long)gw * 32 + lane]);
        acc.x = 2.f * acc.x - u.x; acc.y = 2.f * acc.y - u.y;
        acc.z = 2.f * acc.z - u.z; acc.w = 2.f * acc.w - u.w;
    }
    OUT[(long)gw * 32 + lane] = acc;
}

// ================= weight pre-conversion =================
__global__ void wcvt_kernel(const float* __restrict__ W, __nv_bfloat16* __restrict__ out) {
    int e = blockIdx.x * blockDim.x + threadIdx.x;
    if (e >= 3 * 16384) return;
    int s   = e >> 14;
    int r   = e & 16383;
    int k   = r >> 7;
    int nn  = r & 127;
    float v = W[s * 16384 + (size_t)k * 128 + nn];
    __nv_bfloat16 h = __float2bfloat16(v);
    __nv_bfloat16 l = __float2bfloat16(v - __bfloat162float(h));
    int pos = kpos_even(k & ~1) + (k & 1);
    __nv_bfloat16* o = out + (size_t)s * 34816 + nn * 136 + pos;
    o[0]     = h;
    o[17408] = l;
}

// ================= bf16 mma.sync GEMM =================
// BM=128, BN=128, 8 warps (4M x 2N), warp tile 32x64. 1 CTA/SM.
// Fused precision loop: per k-group load (Ah,Al,Wh,Wl) frags once -> 48 MMAs.
// MODE 0: OUT[row] = relu(acc + bias). MODE 2: red.global into g_sums[batch[row]].
#define APITCH 272
#define SMA_HI 0
#define SMA_LO (128 * APITCH)               // 34816
#define SMW_HI (2 * 128 * APITCH)           // 69632
#define SMW_LO (3 * 128 * APITCH)           // 104448
#define SM_GEMM (4 * 128 * APITCH)          // 139264

__device__ __forceinline__ uint32_t smem_u32(const void* p) {
    uint32_t a;
    asm("{ .reg .u64 t; cvta.to.shared.u64 t, %1; cvt.u32.u64 %0, t; }" : "=r"(a) : "l"(p));
    return a;
}
__device__ __forceinline__ void mma_bf16(float& d0, float& d1, float& d2, float& d3,
                                         uint32_t a0, uint32_t a1, uint32_t a2, uint32_t a3,
                                         uint32_t b0, uint32_t b1) {
    asm volatile("mma.sync.aligned.m16n8k16.row.col.f32.bf16.bf16.f32 "
                 "{%0,%1,%2,%3}, {%4,%5,%6,%7}, {%8,%9}, {%0,%1,%2,%3};"
                 : "+f"(d0), "+f"(d1), "+f"(d2), "+f"(d3)
                 : "r"(a0), "r"(a1), "r"(a2), "r"(a3), "r"(b0), "r"(b1));
}

template <int MODE>
__global__ void __launch_bounds__(256, 1) gemm_mma_kernel(
    const float* __restrict__ S0, const float* __restrict__ S1, const float* __restrict__ S2,
    const __nv_bfloat16* __restrict__ Wc, const float* __restrict__ bias,
    float* __restrict__ OUT, const int* __restrict__ batch, int n)
{
    extern __shared__ __align__(16) char smem[];
    const int tid  = threadIdx.x;
    const int wid  = tid >> 5;
    const int lane = tid & 31;
    const int wm   = wid & 3;          // rows wm*32
    const int wn   = wid >> 2;         // cols wn*64
    const int row0 = blockIdx.x * 128;

    float acc[2][8][4];
#pragma unroll
    for (int i = 0; i < 2; ++i)
#pragma unroll
        for (int j = 0; j < 8; ++j)
#pragma unroll
            for (int c = 0; c < 4; ++c) acc[i][j][c] = 0.0f;

    const int srow  = tid >> 1;           // staging row 0..127
    const int kbase = (tid & 1) * 64;     // staging k half
    const uint32_t wsm = smem_u32(smem + SMW_HI);

    for (int s = 0; s < 3; ++s) {
        const float* A = (s == 0) ? S0 : (s == 1) ? S1 : S2;
        __syncthreads();
        // ---- stage W via cp.async (already interleaved; straight 16B copies) ----
        {
            const char* wsrc = (const char*)(Wc + (size_t)s * 34816);
#pragma unroll
            for (int i = 0; i < 17; ++i) {
                uint32_t dp = wsm + (i * 256 + tid) * 16;
                const char* sp = wsrc + (i * 256 + tid) * 16;
                asm volatile("cp.async.cg.shared.global [%0], [%1], 16;" :: "r"(dp), "l"(sp));
            }
            asm volatile("cp.async.commit_group;" ::: "memory");
        }
        // ---- stage A (fp32 -> bf16 hi/lo, k-interleaved) ----
        {
            uint32_t* ah = (uint32_t*)(smem + SMA_HI + srow * APITCH);
            uint32_t* al = (uint32_t*)(smem + SMA_LO + srow * APITCH);
            const int rg = row0 + srow;
            const float4* arow = (const float4*)(A + (size_t)rg * FDIM + kbase);
#pragma unroll 4
            for (int j = 0; j < 16; ++j) {
                float4 v = (rg < n) ? __ldg(&arow[j]) : make_float4(0.f, 0.f, 0.f, 0.f);
                int k0 = kbase + 4 * j;
                __nv_bfloat16 h0 = __float2bfloat16(v.x), h1 = __float2bfloat16(v.y);
                __nv_bfloat16 h2 = __float2bfloat16(v.z), h3 = __float2bfloat16(v.w);
                __nv_bfloat16 l0 = __float2bfloat16(v.x - __bfloat162float(h0));
                __nv_bfloat16 l1 = __float2bfloat16(v.y - __bfloat162float(h1));
                __nv_bfloat16 l2 = __float2bfloat16(v.z - __bfloat162float(h2));
                __nv_bfloat16 l3 = __float2bfloat16(v.w - __bfloat162float(h3));
                int wA = kpos_even(k0) >> 1;
                int wB = kpos_even(k0 + 2) >> 1;
                union { __nv_bfloat162 b; uint32_t u; } t;
                t.b = __halves2bfloat162(h0, h1); ah[wA] = t.u;
                t.b = __halves2bfloat162(h2, h3); ah[wB] = t.u;
                t.b = __halves2bfloat162(l0, l1); al[wA] = t.u;
                t.b = __halves2bfloat162(l2, l3); al[wB] = t.u;
            }
        }
        asm volatile("cp.async.wait_group 0;" ::: "memory");
        __syncthreads();

        // ---- fused precision loop: Ah*Wh + Al*Wh + Ah*Wl ----
        {
            const char* ah0 = smem + SMA_HI + (wm * 32 + (lane >> 2)) * APITCH + (lane & 3) * 8;
            const char* al0 = smem + SMA_LO + (wm * 32 + (lane >> 2)) * APITCH + (lane & 3) * 8;
            const char* bh0 = smem + SMW_HI + (wn * 64 + (lane >> 2)) * APITCH + (lane & 3) * 8;
            const char* bl0 = smem + SMW_LO + (wn * 64 + (lane >> 2)) * APITCH + (lane & 3) * 8;
#pragma unroll
            for (int g = 0; g < 8; ++g) {
                const int go = g * 32;
                uint2 ah[4], al[4], bh[8], bl[8];
#pragma unroll
                for (int r = 0; r < 4; ++r) {
                    ah[r] = *(const uint2*)(ah0 + r * 8 * APITCH + go);
                    al[r] = *(const uint2*)(al0 + r * 8 * APITCH + go);
                }
#pragma unroll
                for (int j = 0; j < 8; ++j) {
                    bh[j] = *(const uint2*)(bh0 + j * 8 * APITCH + go);
                    bl[j] = *(const uint2*)(bl0 + j * 8 * APITCH + go);
                }
#pragma unroll
                for (int j = 0; j < 8; ++j) {
                    // Ah * Wh
                    mma_bf16(acc[0][j][0], acc[0][j][1], acc[0][j][2], acc[0][j][3],
                             ah[0].x, ah[1].x, ah[0].y, ah[1].y, bh[j].x, bh[j].y);
                    mma_bf16(acc[1][j][0], acc[1][j][1], acc[1][j][2], acc[1][j][3],
                             ah[2].x, ah[3].x, ah[2].y, ah[3].y, bh[j].x, bh[j].y);
                    // Al * Wh
                    mma_bf16(acc[0][j][0], acc[0][j][1], acc[0][j][2], acc[0][j][3],
                             al[0].x, al[1].x, al[0].y, al[1].y, bh[j].x, bh[j].y);
                    mma_bf16(acc[1][j][0], acc[1][j][1], acc[1][j][2], acc[1][j][3],
                             al[2].x, al[3].x, al[2].y, al[3].y, bh[j].x, bh[j].y);
                    // Ah * Wl
                    mma_bf16(acc[0][j][0], acc[0][j][1], acc[0][j][2], acc[0][j][3],
                             ah[0].x, ah[1].x, ah[0].y, ah[1].y, bl[j].x, bl[j].y);
                    mma_bf16(acc[1][j][0], acc[1][j][1], acc[1][j][2], acc[1][j][3],
                             ah[2].x, ah[3].x, ah[2].y, ah[3].y, bl[j].x, bl[j].y);
                }
            }
        }
    }

    // ---- epilogue ----
#pragma unroll
    for (int i = 0; i < 2; ++i) {
        int r0 = row0 + wm * 32 + i * 16 + (lane >> 2);
        int r1 = r0 + 8;
        int g0 = 0, g1 = 0;
        if (MODE == 2) {
            if (r0 < n) g0 = __ldg(&batch[r0]);
            if (r1 < n) g1 = __ldg(&batch[r1]);
        }
#pragma unroll
        for (int j = 0; j < 8; ++j) {
            int col = wn * 64 + j * 8 + (lane & 3) * 2;
            float2 bv = __ldg((const float2*)&bias[col]);
            float2 o0 = make_float2(acc[i][j][0] + bv.x, acc[i][j][1] + bv.y);
            float2 o1 = make_float2(acc[i][j][2] + bv.x, acc[i][j][3] + bv.y);
            if (MODE == 0) {
                o0.x = fmaxf(o0.x, 0.f); o0.y = fmaxf(o0.y, 0.f);
                o1.x = fmaxf(o1.x, 0.f); o1.y = fmaxf(o1.y, 0.f);
                if (r0 < n) *(float2*)&OUT[(size_t)r0 * FDIM + col] = o0;
                if (r1 < n) *(float2*)&OUT[(size_t)r1 * FDIM + col] = o1;
            } else {
                if (r0 < n) {
                    float* p = &g_sums[g0 * FDIM + col];
                    asm volatile("red.global.add.v2.f32 [%0], {%1,%2};"
                                 :: "l"(p), "f"(o0.x), "f"(o0.y) : "memory");
                }
                if (r1 < n) {
                    float* p = &g_sums[g1 * FDIM + col];
                    asm volatile("red.global.add.v2.f32 [%0], {%1,%2};"
                                 :: "l"(p), "f"(o1.x), "f"(o1.y) : "memory");
                }
            }
        }
    }
}

// ================= pooling + classifier =================
__global__ void cnt_kernel(const int* __restrict__ batch, int n) {
    int i = blockIdx.x * blockDim.x + threadIdx.x;
    if (i < n) atomicAdd(&g_cnt[batch[i]], 1.0f);
}
__global__ void final_kernel(const float* __restrict__ Wl, const float* __restrict__ bl,
                             float* __restrict__ out, int ngraphs) {
    int tid = blockIdx.x * blockDim.x + threadIdx.x;
    if (tid >= ngraphs * CLS) return;
    int g = tid / CLS;
    int c = tid % CLS;
    float s = 0.0f;
    const float* sp = &g_sums[g * FDIM];
#pragma unroll 16
    for (int d = 0; d < FDIM; ++d) s = fmaf(sp[d], Wl[d * CLS + c], s);
    float cnt = fmaxf(g_cnt[g], 1.0f);
    out[g * CLS + c] = s / cnt + bl[c];
}

// ---------------------------------------------------------------
extern "C" void kernel_launch(void* const* d_in, const int* in_sizes, int n_in,
                              void* d_out, int out_size) {
    const float* x   = (const float*)d_in[0];
    const int*   ei  = (const int*)  d_in[1];
    const int*   bat = (const int*)  d_in[2];
    const float* W1  = (const float*)d_in[3];
    const float* b1  = (const float*)d_in[4];
    const float* W2  = (const float*)d_in[5];
    const float* b2  = (const float*)d_in[6];
    const float* W3  = (const float*)d_in[7];
    const float* b3  = (const float*)d_in[8];
    const float* Wl  = (const float*)d_in[9];
    const float* bl  = (const float*)d_in[10];
    float* out = (float*)d_out;

    const int n = in_sizes[0] / FDIM;          // 100000
    const int E = in_sizes[1] / 2;             // 1600000
    const int G = out_size / CLS;              // 64
    const int* src = ei;
    const int* dst = ei + E;
    const int ntiles = (n + 127) / 128;

    float *deg, *T1, *T2, *H1, *H2, *sums, *cnt;
    int *rcnt, *fill;
    __nv_bfloat16* Wc;
    cudaGetSymbolAddress((void**)&deg,  g_deg);
    cudaGetSymbolAddress((void**)&rcnt, g_rcnt);
    cudaGetSymbolAddress((void**)&fill, g_fill);
    cudaGetSymbolAddress((void**)&T1,   g_T1);
    cudaGetSymbolAddress((void**)&T2,   g_T2);
    cudaGetSymbolAddress((void**)&H1,   g_H1);
    cudaGetSymbolAddress((void**)&H2,   g_H2);
    cudaGetSymbolAddress((void**)&sums, g_sums);
    cudaGetSymbolAddress((void**)&cnt,  g_cnt);
    cudaGetSymbolAddress((void**)&Wc,   g_Wc);

    cudaFuncSetAttribute(gemm_mma_kernel<0>, cudaFuncAttributeMaxDynamicSharedMemorySize, SM_GEMM);
    cudaFuncSetAttribute(gemm_mma_kernel<2>, cudaFuncAttributeMaxDynamicSharedMemorySize, SM_GEMM);

    const int TB = 256;

    // zeroing + degree/rcnt (one edge pass) + normalization
    cudaMemsetAsync(deg,  0, (size_t)n * sizeof(float));
    cudaMemsetAsync(rcnt, 0, (size_t)n * sizeof(int));
    cudaMemsetAsync(fill, 0, (size_t)n * sizeof(int));
    cudaMemsetAsync(sums, 0, (size_t)G * FDIM * sizeof(float));
    cudaMemsetAsync(cnt,  0, (size_t)G * sizeof(float));
    degcnt_kernel<<<(E + TB - 1) / TB, TB>>>(src, dst, E);
    dinv_kernel<<<(n + TB - 1) / TB, TB>>>(n);

    // CSR build (by dst)
    const int nb = (n + SCAN_B - 1) / SCAN_B;
    scan1_kernel<<<nb, SCAN_B>>>(n);
    scan2_kernel<<<1, 256>>>(nb);
    scan3_kernel<<<(n + TB - 1) / TB, TB>>>(n);
    fill_kernel<<<(E + TB - 1) / TB, TB>>>(src, dst, E);

    // weight pre-conversion + graph counts
    const int wblk = (3 * 16384 + TB - 1) / TB;
    wcvt_kernel<<<wblk, TB>>>(W1, Wc);
    wcvt_kernel<<<wblk, TB>>>(W2, Wc + (size_t)3 * 34816);
    wcvt_kernel<<<wblk, TB>>>(W3, Wc + (size_t)6 * 34816);
    cnt_kernel<<<(n + TB - 1) / TB, TB>>>(bat, n);

    const int propBlocks = (n * 32 + TB - 1) / TB;

    // layer 1
    prop_csr_kernel<0><<<propBlocks, TB>>>((const float4*)x, nullptr, (float4*)T1, n);
    prop_csr_kernel<1><<<propBlocks, TB>>>((const float4*)T1, (const float4*)x, (float4*)T2, n);
    gemm_mma_kernel<0><<<ntiles, 256, SM_GEMM>>>(x, T1, T2, Wc, b1, H1, nullptr, n);
    // layer 2
    prop_csr_kernel<0><<<propBlocks, TB>>>((const float4*)H1, nullptr, (float4*)T1, n);
    prop_csr_kernel<1><<<propBlocks, TB>>>((const float4*)T1, (const float4*)H1, (float4*)T2, n);
    gemm_mma_kernel<0><<<ntiles, 256, SM_GEMM>>>(H1, T1, T2, Wc + (size_t)3 * 34816, b2, H2, nullptr, n);
    // layer 3 (pool fused into epilogue)
    prop_csr_kernel<0><<<propBlocks, TB>>>((const float4*)H2, nullptr, (float4*)T1, n);
    prop_csr_kernel<1><<<propBlocks, TB>>>((const float4*)T1, (const float4*)H2, (float4*)T2, n);
    gemm_mma_kernel<2><<<ntiles, 256, SM_GEMM>>>(H2, T1, T2, Wc + (size_t)6 * 34816, b3, nullptr, bat, n);

    // classifier
    final_kernel<<<(G * CLS + TB - 1) / TB, TB>>>(Wl, bl, out, G);
}